// round 12
// baseline (speedup 1.0000x reference)
#include <cuda_runtime.h>
#include <math.h>
#include <stdint.h>

// Problem dims
#define BB     4
#define TT     12
#define NN     512
#define DIMV   128
#define HH     4
#define DKV    32
#define TOKENS (BB*TT*NN)          // 24576

typedef unsigned long long ull;

// Scratch (no cudaMalloc allowed)
__device__ float g_v[BB*HH*TT*NN*DKV];         // V f32 (pre-transpose)
__device__ float g_x[(size_t)TOKENS*DIMV];     // [b][t][n][h*dk]
__device__ float g_am[(size_t)BB*TT*NN*NN];    // [b][t][n][j] fused mask/adjm
__device__ unsigned g_wh[4*128*64];            // W hi bf16 pairs
__device__ unsigned g_wl[4*128*64];            // W lo bf16 pairs
__device__ unsigned g_qp[BB*HH*TT*NN*32];      // Q packed: [n][hi0..15 | lo0..15]
__device__ unsigned g_kp[BB*HH*TT*NN*32];      // K packed likewise
__device__ unsigned g_vp[(size_t)BB*HH*TT*256*64]; // V^T packed: [jp][hi dk0..31 | lo dk0..31]

// ---------------------------------------------------------------------------
// bf16 mma helpers (sm_80+; valid on plain sm_100 target)
// ---------------------------------------------------------------------------
__device__ __forceinline__ void mma_bf16(float* d, const unsigned* a, const unsigned* b) {
    asm volatile(
        "mma.sync.aligned.m16n8k16.row.col.f32.bf16.bf16.f32 "
        "{%0,%1,%2,%3}, {%4,%5,%6,%7}, {%8,%9}, {%0,%1,%2,%3};"
        : "+f"(d[0]), "+f"(d[1]), "+f"(d[2]), "+f"(d[3])
        : "r"(a[0]), "r"(a[1]), "r"(a[2]), "r"(a[3]), "r"(b[0]), "r"(b[1]));
}
__device__ __forceinline__ unsigned bftrunc2(float v0, float v1) {
    return __byte_perm(__float_as_uint(v0), __float_as_uint(v1), 0x7632);
}
__device__ __forceinline__ unsigned bfpack2(float l0, float l1) {
    unsigned d; asm("cvt.rn.bf16x2.f32 %0, %1, %2;" : "=r"(d) : "f"(l1), "f"(l0));
    return d;
}
__device__ __forceinline__ float truncbf(float v) {
    return __uint_as_float(__float_as_uint(v) & 0xFFFF0000u);
}
__device__ __forceinline__ void cpa16(unsigned dst, const unsigned* src) {
    asm volatile("cp.async.cg.shared.global [%0], [%1], 16;" :: "r"(dst), "l"(src));
}
#define CP_COMMIT() asm volatile("cp.async.commit_group;" ::: "memory")
#define CP_WAIT0()  asm volatile("cp.async.wait_group 0;" ::: "memory")

// ---------------------------------------------------------------------------
// Prep kernels
// ---------------------------------------------------------------------------
__global__ __launch_bounds__(256)
void prep_kernel(const int* __restrict__ mask, const float* __restrict__ adjm)
{
    const size_t i = (size_t)blockIdx.x * 256 + threadIdx.x;
    const int4   m = __ldg(&((const int4*)mask)[i]);
    const float4 a = __ldg(&((const float4*)adjm)[i]);
    float4 o;
    o.x = m.x ? -1.0f : a.x;
    o.y = m.y ? -1.0f : a.y;
    o.z = m.z ? -1.0f : a.z;
    o.w = m.w ? -1.0f : a.w;
    ((float4*)g_am)[i] = o;
}

__global__ __launch_bounds__(256)
void prep_w(const float* __restrict__ Wq, const float* __restrict__ Wk,
            const float* __restrict__ Wv, const float* __restrict__ Wp)
{
    const int idx = blockIdx.x * 256 + threadIdx.x;
    const int which = idx >> 13;
    const int rem = idx & 8191;
    const float* W = (which == 0) ? Wq : (which == 1) ? Wk : (which == 2) ? Wv : Wp;
    const float2 v = __ldg(&((const float2*)W)[rem]);
    g_wh[idx] = bftrunc2(v.x, v.y);
    g_wl[idx] = bfpack2(v.x - truncbf(v.x), v.y - truncbf(v.y));
}

// V f32 [bht][j][dk] -> packed j-pair words [bht][jp][hi dk0..31 | lo dk0..31]
__global__ __launch_bounds__(256)
void prep_v()
{
    const int bht = blockIdx.x;          // 0..191
    const int jp = threadIdx.x;          // 0..255
    const float* src = g_v + (size_t)bht * NN * DKV + (size_t)(2 * jp) * DKV;
    unsigned* dst = g_vp + (size_t)bht * 256 * 64 + (size_t)jp * 64;
#pragma unroll 4
    for (int dk4 = 0; dk4 < 8; ++dk4) {
        const float4 a = *(const float4*)(src + dk4 * 4);          // row 2jp
        const float4 c = *(const float4*)(src + DKV + dk4 * 4);    // row 2jp+1
        const float av[4] = {a.x, a.y, a.z, a.w};
        const float cv[4] = {c.x, c.y, c.z, c.w};
        unsigned hi[4], lo[4];
#pragma unroll
        for (int e = 0; e < 4; ++e) {
            hi[e] = bftrunc2(av[e], cv[e]);
            lo[e] = bfpack2(av[e] - truncbf(av[e]), cv[e] - truncbf(cv[e]));
        }
        *(uint4*)(dst + dk4 * 4)      = make_uint4(hi[0], hi[1], hi[2], hi[3]);
        *(uint4*)(dst + 32 + dk4 * 4) = make_uint4(lo[0], lo[1], lo[2], lo[3]);
    }
}

// ---------------------------------------------------------------------------
// Projection GEMM via bf16x3 mma. QKV: which 0/1 write packed bf16 hi/lo to
// g_qp/g_kp; which 2 writes f32 g_v (prep_v transposes). QKV=false -> d_out.
// ---------------------------------------------------------------------------
#define XP2 68
#define PROJ_SMEM (2 * 128 * XP2 * 4)   // 69632 B

template<bool QKV>
__global__ __launch_bounds__(256)
void proj_mma(const float* __restrict__ x0, const float* __restrict__ x1,
              const float* __restrict__ x2,
              const float* __restrict__ b0, const float* __restrict__ b1,
              const float* __restrict__ b2,
              float* __restrict__ Yflat)
{
    extern __shared__ unsigned smu[];
    unsigned* Xhi = smu;
    unsigned* Xlo = smu + 128 * XP2;

    const int tid = threadIdx.x;
    const int wid = tid >> 5;
    const int lane = tid & 31;
    const int g = lane >> 2, r = lane & 3;
    const int token0 = blockIdx.x * 128;
    const int which = QKV ? blockIdx.y : 3;

    const float* X    = QKV ? (which == 0 ? x0 : which == 1 ? x1 : x2) : g_x;
    const float* bias = QKV ? (which == 0 ? b0 : which == 1 ? b1 : b2) : b0;

    for (int idx = tid; idx < 128 * 32; idx += 256) {
        const int row = idx >> 5, c4 = idx & 31;
        const float4 v = __ldg(&((const float4*)X)[(size_t)(token0 + row) * 32 + c4]);
        Xhi[row * XP2 + c4 * 2]     = bftrunc2(v.x, v.y);
        Xhi[row * XP2 + c4 * 2 + 1] = bftrunc2(v.z, v.w);
        Xlo[row * XP2 + c4 * 2]     = bfpack2(v.x - truncbf(v.x), v.y - truncbf(v.y));
        Xlo[row * XP2 + c4 * 2 + 1] = bfpack2(v.z - truncbf(v.z), v.w - truncbf(v.w));
    }
    __syncthreads();

    const int mw = wid & 3, nw = wid >> 2;
    const int m0 = mw * 32;
    const int jb = nw * 64;
    const unsigned* wh = g_wh + which * 8192;
    const unsigned* wl = g_wl + which * 8192;

    float sacc[2][8][4];
#pragma unroll
    for (int mi = 0; mi < 2; ++mi)
#pragma unroll
        for (int ni = 0; ni < 8; ++ni)
#pragma unroll
            for (int c = 0; c < 4; ++c) sacc[mi][ni][c] = 0.0f;

#pragma unroll 2
    for (int kk = 0; kk < 8; ++kk) {
        unsigned ah[2][4], al[2][4];
#pragma unroll
        for (int mi = 0; mi < 2; ++mi) {
            const int base = (m0 + mi * 16 + g) * XP2 + kk * 8 + r;
            ah[mi][0] = Xhi[base];       ah[mi][1] = Xhi[base + 8 * XP2];
            ah[mi][2] = Xhi[base + 4];   ah[mi][3] = Xhi[base + 8 * XP2 + 4];
            al[mi][0] = Xlo[base];       al[mi][1] = Xlo[base + 8 * XP2];
            al[mi][2] = Xlo[base + 4];   al[mi][3] = Xlo[base + 8 * XP2 + 4];
        }
#pragma unroll
        for (int ni = 0; ni < 8; ++ni) {
            const int wb = (jb + ni * 8 + g) * 64 + kk * 8 + r;
            unsigned bh[2], bl[2];
            bh[0] = __ldg(&wh[wb]); bh[1] = __ldg(&wh[wb + 4]);
            bl[0] = __ldg(&wl[wb]); bl[1] = __ldg(&wl[wb + 4]);
#pragma unroll
            for (int mi = 0; mi < 2; ++mi) {
                mma_bf16(sacc[mi][ni], ah[mi], bh);
                mma_bf16(sacc[mi][ni], ah[mi], bl);
                mma_bf16(sacc[mi][ni], al[mi], bh);
            }
        }
    }

#pragma unroll
    for (int ni = 0; ni < 8; ++ni) {
        const int col = jb + ni * 8 + 2 * r;
        const float bb0 = __ldg(&bias[col]), bb1 = __ldg(&bias[col + 1]);
#pragma unroll
        for (int mi = 0; mi < 2; ++mi) {
            const int rowl = m0 + mi * 16 + g;
            const int rowh = rowl + 8;
            const float* s = sacc[mi][ni];
            const float2 vl = make_float2(s[0] + bb0, s[1] + bb1);
            const float2 vh = make_float2(s[2] + bb0, s[3] + bb1);
            if (QKV) {
                const int hh = col >> 5, dd = col & 31, pr = dd >> 1;
                const int tkl = token0 + rowl, tkh = token0 + rowh;
                const int nl = tkl & (NN - 1), btl = tkl >> 9;
                const int nh = tkh & (NN - 1), bth = tkh >> 9;
                const int bl_ = btl / TT, tl = btl - bl_ * TT;
                const int bh_ = bth / TT, th = bth - bh_ * TT;
                const size_t il = (((size_t)bl_ * HH + hh) * TT + tl) * NN + nl;
                const size_t ih = (((size_t)bh_ * HH + hh) * TT + th) * NN + nh;
                if (which == 2) {
                    *(float2*)&g_v[il * DKV + dd] = vl;
                    *(float2*)&g_v[ih * DKV + dd] = vh;
                } else {
                    unsigned* Yp = (which == 0) ? g_qp : g_kp;
                    Yp[il * 32 + pr]      = bftrunc2(vl.x, vl.y);
                    Yp[il * 32 + 16 + pr] = bfpack2(vl.x - truncbf(vl.x), vl.y - truncbf(vl.y));
                    Yp[ih * 32 + pr]      = bftrunc2(vh.x, vh.y);
                    Yp[ih * 32 + 16 + pr] = bfpack2(vh.x - truncbf(vh.x), vh.y - truncbf(vh.y));
                }
            } else {
                *(float2*)&Yflat[(size_t)(token0 + rowl) * DIMV + col] = vl;
                *(float2*)&Yflat[(size_t)(token0 + rowh) * DIMV + col] = vh;
            }
        }
    }
}

// ---------------------------------------------------------------------------
// Attention v4: pre-split packed operands + cp.async staging (no conversion
// in the hot loop). Block = 64 rows x (b,h,t); 128 thr / 4 warps (2M x 2J).
// P kept in registers (S-frag reuse). smem 45KB -> 3 CTAs/SM.
// ---------------------------------------------------------------------------
#define QPs 36
#define KPs 36
#define VPs 72
#define OF_QP 0                    // 64*36  = 2304
#define OF_KP 2304                 // 128*36 = 4608
#define OF_VP 6912                 // 64*72  = 4608
#define AT_UINTS 11520
#define AT_SMEM (AT_UINTS * 4)     // 46080 B

__global__ __launch_bounds__(128, 3)
void attn_mma()
{
    extern __shared__ unsigned smu[];
    unsigned* Qp = smu + OF_QP;
    unsigned* Kp = smu + OF_KP;
    unsigned* Vp = smu + OF_VP;

    const int tid  = threadIdx.x;
    const int wid  = tid >> 5;
    const int lane = tid & 31;
    const int g = lane >> 2, r = lane & 3;

    const int m = blockIdx.x, t = blockIdx.y;
    const int h = blockIdx.z & 3, b = blockIdx.z >> 2;
    const int n0 = m * 64;
    const int kvidx = (b * HH + h) * TT + t;

    const unsigned* qsrc = g_qp + (size_t)kvidx * NN * 32;
    const unsigned* ksrc = g_kp + (size_t)kvidx * NN * 32;
    const unsigned* vsrc = g_vp + (size_t)kvidx * 256 * 64;
    const float* amb = g_am + (size_t)(b * TT + t) * NN * NN;

    // ---- stage Q once (cp.async; completes with first chunk's wait) ----
    {
        const int row = tid >> 1, half = tid & 1;
        const unsigned dst = (unsigned)__cvta_generic_to_shared(Qp + row * QPs + half * 16);
        const unsigned* src = qsrc + (size_t)(n0 + row) * 32 + half * 16;
#pragma unroll
        for (int i = 0; i < 4; ++i) cpa16(dst + i * 16, src + i * 4);
        CP_COMMIT();
    }

    const int mw = wid & 1, nw = wid >> 1;
    const int m0 = mw * 32;
    const int jb = nw * 64;

    const float scale = 0.1767766952966369f;   // 1/sqrt(32)

    float oacc[2][4][4];
#pragma unroll
    for (int i = 0; i < 2; ++i)
#pragma unroll
        for (int j = 0; j < 4; ++j)
#pragma unroll
            for (int c = 0; c < 4; ++c) oacc[i][j][c] = 0.0f;
    float srow[4] = {0.f, 0.f, 0.f, 0.f};

    for (int ch = 0; ch < 4; ++ch) {
        const int j0 = ch * 128;
        __syncthreads();   // prior chunk's smem reads complete

        // ---- stage K chunk (128 rows x 128B) ----
        {
            const unsigned dst = (unsigned)__cvta_generic_to_shared(Kp + tid * KPs);
            const unsigned* src = ksrc + (size_t)(j0 + tid) * 32;
#pragma unroll
            for (int i = 0; i < 8; ++i) cpa16(dst + i * 16, src + i * 4);
        }
        // ---- stage V chunk (64 jp rows x 256B) ----
        {
            const int jp = tid >> 1, half = tid & 1;
            const unsigned dst = (unsigned)__cvta_generic_to_shared(Vp + jp * VPs + half * 32);
            const unsigned* src = vsrc + (size_t)(j0 / 2 + jp) * 64 + half * 32;
#pragma unroll
            for (int i = 0; i < 8; ++i) cpa16(dst + i * 16, src + i * 4);
        }
        CP_COMMIT();

        // ---- am prefetch (LDG latency overlaps cp.async) ----
        float2 amL[2][8], amH[2][8];
#pragma unroll
        for (int mi = 0; mi < 2; ++mi) {
            const int rowl = m0 + mi * 16 + g;
            const float* aL = amb + (size_t)(n0 + rowl) * NN + j0;
            const float* aH = amb + (size_t)(n0 + rowl + 8) * NN + j0;
#pragma unroll
            for (int ni = 0; ni < 8; ++ni) {
                const int jl = jb + ni * 8 + 2 * r;
                amL[mi][ni] = __ldg((const float2*)(aL + jl));
                amH[mi][ni] = __ldg((const float2*)(aH + jl));
            }
        }

        CP_WAIT0();
        __syncthreads();

        // ---- GEMM1: S = Q.K^T (bf16x3; operands pre-split) ----
        float sacc[2][8][4];
#pragma unroll
        for (int mi = 0; mi < 2; ++mi)
#pragma unroll
            for (int ni = 0; ni < 8; ++ni)
#pragma unroll
                for (int c = 0; c < 4; ++c) sacc[mi][ni][c] = 0.0f;

#pragma unroll
        for (int kk = 0; kk < 2; ++kk) {
            unsigned ah[2][4], al[2][4];
#pragma unroll
            for (int mi = 0; mi < 2; ++mi) {
                const int base = (m0 + mi * 16 + g) * QPs + kk * 8 + r;
                ah[mi][0] = Qp[base];            ah[mi][1] = Qp[base + 8 * QPs];
                ah[mi][2] = Qp[base + 4];        ah[mi][3] = Qp[base + 8 * QPs + 4];
                al[mi][0] = Qp[base + 16];       al[mi][1] = Qp[base + 8 * QPs + 16];
                al[mi][2] = Qp[base + 20];       al[mi][3] = Qp[base + 8 * QPs + 20];
            }
#pragma unroll
            for (int ni = 0; ni < 8; ++ni) {
                const int bb = (jb + ni * 8 + g) * KPs + kk * 8 + r;
                unsigned bh[2], bl[2];
                bh[0] = Kp[bb];      bh[1] = Kp[bb + 4];
                bl[0] = Kp[bb + 16]; bl[1] = Kp[bb + 20];
#pragma unroll
                for (int mi = 0; mi < 2; ++mi) {
                    mma_bf16(sacc[mi][ni], ah[mi], bh);
                    mma_bf16(sacc[mi][ni], ah[mi], bl);
                    mma_bf16(sacc[mi][ni], al[mi], bh);
                }
            }
        }

        // ---- epilogue in registers ----
        unsigned wHp[2][8][2], wLp[2][8][2];
#pragma unroll
        for (int mi = 0; mi < 2; ++mi) {
#pragma unroll
            for (int ni = 0; ni < 8; ++ni) {
                const float a00 = amL[mi][ni].x, a01 = amL[mi][ni].y;
                const float a10 = amH[mi][ni].x, a11 = amH[mi][ni].y;
                const float* s = sacc[mi][ni];
                const float p00 = (a00 >= 0.f) ? __expf(s[0] * scale) : 0.f;
                const float p01 = (a01 >= 0.f) ? __expf(s[1] * scale) : 0.f;
                const float p10 = (a10 >= 0.f) ? __expf(s[2] * scale) : 0.f;
                const float p11 = (a11 >= 0.f) ? __expf(s[3] * scale) : 0.f;
                srow[mi * 2 + 0] += p00 + p01;
                srow[mi * 2 + 1] += p10 + p11;
                const float w00 = p00 * a00, w01 = p01 * a01;
                const float w10 = p10 * a10, w11 = p11 * a11;
                wHp[mi][ni][0] = bftrunc2(w00, w01);
                wLp[mi][ni][0] = bfpack2(w00 - truncbf(w00), w01 - truncbf(w01));
                wHp[mi][ni][1] = bftrunc2(w10, w11);
                wLp[mi][ni][1] = bfpack2(w10 - truncbf(w10), w11 - truncbf(w11));
            }
        }

        // ---- GEMM2: O += P.V over this warp's 64-j slice (bf16x3) ----
#pragma unroll
        for (int kk = 0; kk < 4; ++kk) {
            const int vrow = nw * 32 + kk * 8 + r;
#pragma unroll
            for (int mi = 0; mi < 2; ++mi) {
                unsigned aH[4] = {wHp[mi][2*kk][0], wHp[mi][2*kk][1],
                                  wHp[mi][2*kk+1][0], wHp[mi][2*kk+1][1]};
                unsigned aL[4] = {wLp[mi][2*kk][0], wLp[mi][2*kk][1],
                                  wLp[mi][2*kk+1][0], wLp[mi][2*kk+1][1]};
#pragma unroll
                for (int ni = 0; ni < 4; ++ni) {
                    const int n = ni * 8 + g;
                    unsigned bvh[2], bvl[2];
                    bvh[0] = Vp[vrow * VPs + n];
                    bvh[1] = Vp[(vrow + 4) * VPs + n];
                    bvl[0] = Vp[vrow * VPs + 32 + n];
                    bvl[1] = Vp[(vrow + 4) * VPs + 32 + n];
                    mma_bf16(oacc[mi][ni], aH, bvh);
                    mma_bf16(oacc[mi][ni], aH, bvl);
                    mma_bf16(oacc[mi][ni], aL, bvh);
                }
            }
        }
    }

    // ---- combine j-groups; normalize; write ----
    __syncthreads();                                  // reuse K region
    float* OB    = (float*)(smu + OF_KP);             // [64][32]
    float* rows2 = (float*)(smu + OF_KP + 2048);      // [2][64]

#pragma unroll
    for (int i = 0; i < 4; ++i) {
        srow[i] += __shfl_xor_sync(0xFFFFFFFFu, srow[i], 1);
        srow[i] += __shfl_xor_sync(0xFFFFFFFFu, srow[i], 2);
    }
    if (r == 0) {
#pragma unroll
        for (int mi = 0; mi < 2; ++mi) {
            rows2[nw * 64 + m0 + mi * 16 + g]     = srow[mi * 2 + 0];
            rows2[nw * 64 + m0 + mi * 16 + g + 8] = srow[mi * 2 + 1];
        }
    }
    if (nw == 1) {
#pragma unroll
        for (int mi = 0; mi < 2; ++mi) {
            const int rowl = m0 + mi * 16 + g;
#pragma unroll
            for (int ni = 0; ni < 4; ++ni) {
                const int col = ni * 8 + 2 * r;
                const float* o = oacc[mi][ni];
                *(float2*)(OB + rowl * 32 + col)       = make_float2(o[0], o[1]);
                *(float2*)(OB + (rowl + 8) * 32 + col) = make_float2(o[2], o[3]);
            }
        }
    }
    __syncthreads();

    if (nw == 0) {
        const size_t xbase = ((size_t)(b * TT + t) * NN + n0) * DIMV + h * DKV;
#pragma unroll
        for (int mi = 0; mi < 2; ++mi) {
            const int rowl = m0 + mi * 16 + g;
            const int rowh = rowl + 8;
            const float il = 1.0f / (rows2[rowl] + rows2[64 + rowl]);
            const float ih = 1.0f / (rows2[rowh] + rows2[64 + rowh]);
#pragma unroll
            for (int ni = 0; ni < 4; ++ni) {
                const int col = ni * 8 + 2 * r;
                const float* o = oacc[mi][ni];
                const float2 pl = *(const float2*)(OB + rowl * 32 + col);
                const float2 ph = *(const float2*)(OB + rowh * 32 + col);
                *(float2*)(g_x + xbase + (size_t)rowl * DIMV + col) =
                    make_float2((o[0] + pl.x) * il, (o[1] + pl.y) * il);
                *(float2*)(g_x + xbase + (size_t)rowh * DIMV + col) =
                    make_float2((o[2] + ph.x) * ih, (o[3] + ph.y) * ih);
            }
        }
    }
}

// ---------------------------------------------------------------------------
extern "C" void kernel_launch(void* const* d_in, const int* in_sizes, int n_in,
                              void* d_out, int out_size)
{
    const float* query = (const float*)d_in[0];
    const float* key_  = (const float*)d_in[1];
    const float* value = (const float*)d_in[2];
    const int*   mask  = (const int*)  d_in[3];
    const float* adjm  = (const float*)d_in[4];
    const float* Wq = (const float*)d_in[5];  const float* bq = (const float*)d_in[6];
    const float* Wk = (const float*)d_in[7];  const float* bk = (const float*)d_in[8];
    const float* Wv = (const float*)d_in[9];  const float* bv = (const float*)d_in[10];
    const float* Wp = (const float*)d_in[11]; const float* bp = (const float*)d_in[12];
    float* out = (float*)d_out;

    static bool attrs_set = false;
    if (!attrs_set) {
        cudaFuncSetAttribute(proj_mma<true>,
                             cudaFuncAttributeMaxDynamicSharedMemorySize, PROJ_SMEM);
        cudaFuncSetAttribute(proj_mma<false>,
                             cudaFuncAttributeMaxDynamicSharedMemorySize, PROJ_SMEM);
        cudaFuncSetAttribute(attn_mma,
                             cudaFuncAttributeMaxDynamicSharedMemorySize, AT_SMEM);
        attrs_set = true;
    }

    prep_kernel<<<(BB*TT*NN*NN/4) / 256, 256>>>(mask, adjm);
    prep_w<<<(4*128*64) / 256, 256>>>(Wq, Wk, Wv, Wp);

    proj_mma<true><<<dim3(TOKENS/128, 3), 256, PROJ_SMEM>>>(
        query, key_, value, bq, bk, bv, out);

    prep_v<<<BB*HH*TT, 256>>>();

    attn_mma<<<dim3(8, TT, HH*BB), 128, AT_SMEM>>>();

    proj_mma<false><<<dim3(TOKENS/128), 256, PROJ_SMEM>>>(
        nullptr, nullptr, nullptr, bp, nullptr, nullptr, out);
}